// round 4
// baseline (speedup 1.0000x reference)
#include <cuda_runtime.h>
#include <cuda_bf16.h>
#include <cstdint>

#define DD     1024
#define NSYM   32
#define FF     1024
#define HALF_F 512
#define GRP    64        // CTAs per direction
#define NTHR   256
#define COLS_PER_CTA 16
#define ROWS_PER_CTA 16
#define SV_PAD(j) ((j) + ((j) >> 5))   // +1 float pad per 32 floats

__device__ __nv_bfloat16 g_core_bf[(size_t)NSYM * DD * DD];  // 64 MB, L2-resident
__device__ float g_v[2][DD];
__device__ float g_u[2][DD];

struct Flag { int v; int pad[31]; };     // 128B-isolated per-CTA flags
__device__ Flag g_flag_f[GRP];
__device__ Flag g_flag_b[GRP];

// ---------------------------------------------------------------------------
__device__ __forceinline__ int ld_acquire(const int* p) {
    int v;
    asm volatile("ld.acquire.gpu.b32 %0, [%1];" : "=r"(v) : "l"(p) : "memory");
    return v;
}
__device__ __forceinline__ void st_relaxed(int* p, int v) {
    asm volatile("st.relaxed.gpu.b32 [%0], %1;" :: "l"(p), "r"(v) : "memory");
}
__device__ __forceinline__ void fence_acqrel_gpu() {
    asm volatile("fence.acq_rel.gpu;" ::: "memory");
}

// ---------------------------------------------------------------------------
// fp32 -> bf16 conversion of the 32 core matrices (192 MB traffic, ~31us)
// ---------------------------------------------------------------------------
__global__ void convert_core_kernel(const float* __restrict__ core) {
    size_t i = ((size_t)blockIdx.x * NTHR + threadIdx.x) * 4;
    float4 f = *reinterpret_cast<const float4*>(core + i);
    __nv_bfloat162 lo = __floats2bfloat162_rn(f.x, f.y);
    __nv_bfloat162 hi = __floats2bfloat162_rn(f.z, f.w);
    uint2 o;
    o.x = *reinterpret_cast<unsigned*>(&lo);
    o.y = *reinterpret_cast<unsigned*>(&hi);
    *reinterpret_cast<uint2*>(g_core_bf + i) = o;
}

// ---------------------------------------------------------------------------
__global__ void init_kernel(const float* __restrict__ left,
                            const float* __restrict__ right) {
    int t = threadIdx.x;
    if (t < DD) {
        g_v[0][t] = left[t];
        g_u[0][t] = right[t];
    }
    if (t < GRP) {
        g_flag_f[t].v = 0;
        g_flag_b[t].v = 0;
    }
}

// ---------------------------------------------------------------------------
// Persistent chain: blocks 0..63 forward (v <- v M), 64..127 backward (u <- M u).
// Distributed-flag barrier (acquire polls), matrix loads double-buffered one
// step ahead so the L2 burst overlaps compute instead of the critical path.
// ---------------------------------------------------------------------------
__global__ __launch_bounds__(NTHR, 1)
void chain_kernel(const int* __restrict__ x, float* __restrict__ out) {
    __shared__ int   sx[HALF_F];
    __shared__ float svec[DD + DD / 32];
    __shared__ float red[8][16];

    const int tid = threadIdx.x;
    const bool is_fwd = (blockIdx.x < GRP);

    if (is_fwd) {
        // ============================ FORWARD ==============================
        const int b  = blockIdx.x;
        const int jb = b * COLS_PER_CTA;

        for (int i = tid; i < HALF_F; i += NTHR) sx[i] = x[i];
        __syncthreads();

        const int q = tid & 3;    // column quad
        const int g = tid >> 2;   // row group 0..63; rows g + 64*i

        const uint2* mbase = reinterpret_cast<const uint2*>(
            g_core_bf + (size_t)g * DD + jb + 4 * q);
        const size_t symstride = (size_t)DD * DD / 4;   // uint2 units
        const size_t rowstride = (size_t)64 * DD / 4;

        uint2 pre[2][16];
        // prime the pipeline: prefetch matrix slice for step 0
        {
            const uint2* mp = mbase + (size_t)sx[0] * symstride;
#pragma unroll
            for (int i = 0; i < 16; ++i) pre[0][i] = __ldg(mp + (size_t)i * rowstride);
        }

        for (int s = 0; s < HALF_F; ++s) {
            // ---- barrier: all fwd CTAs finished step s-1 (acquire polls)
            if (tid < 32) {
                const int* fa = &g_flag_f[tid].v;
                const int* fb = &g_flag_f[tid + 32].v;
                while (!__all_sync(0xffffffffu,
                                   ld_acquire(fa) >= s && ld_acquire(fb) >= s)) { }
            }
            __syncthreads();

            // ---- stage FULL v (1024 floats) into smem (critical path)
            const float* vcur = g_v[s & 1];
            {
                int j0 = 4 * tid;
                float4 t4 = __ldcg(reinterpret_cast<const float4*>(vcur + j0));
                svec[SV_PAD(j0) + 0] = t4.x;
                svec[SV_PAD(j0) + 1] = t4.y;
                svec[SV_PAD(j0) + 2] = t4.z;
                svec[SV_PAD(j0) + 3] = t4.w;
            }

            // ---- issue prefetch for step s+1 (overlaps compute + next barrier)
            {
                int snext = (s + 1 < HALF_F) ? s + 1 : s;
                const uint2* mp = mbase + (size_t)sx[snext] * symstride;
                uint2* dst = pre[(s + 1) & 1];
#pragma unroll
                for (int i = 0; i < 16; ++i) dst[i] = __ldg(mp + (size_t)i * rowstride);
            }
            __syncthreads();

            // ---- accumulate 4 output columns over 16 rows
            const uint2* cur = pre[s & 1];
            float a0 = 0.f, a1 = 0.f, a2 = 0.f, a3 = 0.f;
#pragma unroll
            for (int i = 0; i < 16; ++i) {
                float vv = svec[SV_PAD(g + 64 * i)];
                uint2 m = cur[i];
                a0 += vv * __uint_as_float(m.x << 16);
                a1 += vv * __uint_as_float(m.x & 0xffff0000u);
                a2 += vv * __uint_as_float(m.y << 16);
                a3 += vv * __uint_as_float(m.y & 0xffff0000u);
            }
#pragma unroll
            for (int off = 16; off >= 4; off >>= 1) {
                a0 += __shfl_down_sync(0xffffffffu, a0, off);
                a1 += __shfl_down_sync(0xffffffffu, a1, off);
                a2 += __shfl_down_sync(0xffffffffu, a2, off);
                a3 += __shfl_down_sync(0xffffffffu, a3, off);
            }
            const int lane = tid & 31, w = tid >> 5;
            if (lane < 4) {
                red[w][lane * 4 + 0] = a0;
                red[w][lane * 4 + 1] = a1;
                red[w][lane * 4 + 2] = a2;
                red[w][lane * 4 + 3] = a3;
            }
            __syncthreads();

            float* vnext = g_v[(s + 1) & 1];
            if (tid < 16) {
                float sum = 0.f;
#pragma unroll
                for (int w2 = 0; w2 < 8; ++w2) sum += red[w2][tid];
                __stcg(&vnext[jb + tid], sum);
            }
            __syncthreads();
            if (tid == 0) {
                fence_acqrel_gpu();                 // release our v writes
                st_relaxed(&g_flag_f[b].v, s + 1);
            }
        }
    } else {
        // ============================ BACKWARD =============================
        const int c  = blockIdx.x - GRP;
        const int kb = c * ROWS_PER_CTA;

        for (int i = tid; i < HALF_F; i += NTHR) sx[i] = x[(FF - 1) - i];
        __syncthreads();

        const int r  = tid >> 4;   // row within slice
        const int ch = tid & 15;   // 64-col chunk

        const uint4* mbase = reinterpret_cast<const uint4*>(
            g_core_bf + (size_t)(kb + r) * DD + ch * 64);
        const size_t symstride = (size_t)DD * DD / 8;   // uint4 units

        uint4 pre[2][8];
        {
            const uint4* mp = mbase + (size_t)sx[0] * symstride;
#pragma unroll
            for (int i = 0; i < 8; ++i) pre[0][i] = __ldg(mp + i);
        }

        for (int s = 0; s < HALF_F; ++s) {
            if (tid < 32) {
                const int* fa = &g_flag_b[tid].v;
                const int* fb = &g_flag_b[tid + 32].v;
                while (!__all_sync(0xffffffffu,
                                   ld_acquire(fa) >= s && ld_acquire(fb) >= s)) { }
            }
            __syncthreads();

            const float* ucur = g_u[s & 1];
            {
                int j0 = 4 * tid;
                float4 t4 = __ldcg(reinterpret_cast<const float4*>(ucur + j0));
                svec[SV_PAD(j0) + 0] = t4.x;
                svec[SV_PAD(j0) + 1] = t4.y;
                svec[SV_PAD(j0) + 2] = t4.z;
                svec[SV_PAD(j0) + 3] = t4.w;
            }

            {
                int snext = (s + 1 < HALF_F) ? s + 1 : s;
                const uint4* mp = mbase + (size_t)sx[snext] * symstride;
                uint4* dst = pre[(s + 1) & 1];
#pragma unroll
                for (int i = 0; i < 8; ++i) dst[i] = __ldg(mp + i);
            }
            __syncthreads();

            const uint4* cur = pre[s & 1];
            float acc = 0.f;
#pragma unroll
            for (int i = 0; i < 8; ++i) {
                const int j0 = ch * 64 + i * 8;
                uint4 m = cur[i];
                acc += svec[SV_PAD(j0 + 0)] * __uint_as_float(m.x << 16);
                acc += svec[SV_PAD(j0 + 1)] * __uint_as_float(m.x & 0xffff0000u);
                acc += svec[SV_PAD(j0 + 2)] * __uint_as_float(m.y << 16);
                acc += svec[SV_PAD(j0 + 3)] * __uint_as_float(m.y & 0xffff0000u);
                acc += svec[SV_PAD(j0 + 4)] * __uint_as_float(m.z << 16);
                acc += svec[SV_PAD(j0 + 5)] * __uint_as_float(m.z & 0xffff0000u);
                acc += svec[SV_PAD(j0 + 6)] * __uint_as_float(m.w << 16);
                acc += svec[SV_PAD(j0 + 7)] * __uint_as_float(m.w & 0xffff0000u);
            }
#pragma unroll
            for (int off = 8; off >= 1; off >>= 1)
                acc += __shfl_down_sync(0xffffffffu, acc, off);

            float* unext = g_u[(s + 1) & 1];
            if ((tid & 15) == 0)
                __stcg(&unext[kb + r], acc);
            __syncthreads();
            if (tid == 0) {
                fence_acqrel_gpu();
                st_relaxed(&g_flag_b[c].v, s + 1);
            }
        }
    }

    // ======================== FINAL COMBINE (block 0) ======================
    if (blockIdx.x == 0) {
        if (tid < 32) {
            const int* f0 = &g_flag_f[tid].v;
            const int* f1 = &g_flag_f[tid + 32].v;
            const int* f2 = &g_flag_b[tid].v;
            const int* f3 = &g_flag_b[tid + 32].v;
            while (!__all_sync(0xffffffffu,
                               ld_acquire(f0) >= HALF_F && ld_acquire(f1) >= HALF_F &&
                               ld_acquire(f2) >= HALF_F && ld_acquire(f3) >= HALF_F)) { }
        }
        __syncthreads();

        float p = 0.f;
        for (int i = tid; i < DD; i += NTHR)
            p += __ldcg(&g_v[0][i]) * __ldcg(&g_u[0][i]);
#pragma unroll
        for (int off = 16; off >= 1; off >>= 1)
            p += __shfl_down_sync(0xffffffffu, p, off);

        __shared__ float fin[8];
        if ((tid & 31) == 0) fin[tid >> 5] = p;
        __syncthreads();
        if (tid == 0) {
            float t = 0.f;
#pragma unroll
            for (int w2 = 0; w2 < 8; ++w2) t += fin[w2];
            out[0] = t;
        }
    }
}

// ---------------------------------------------------------------------------
extern "C" void kernel_launch(void* const* d_in, const int* in_sizes, int n_in,
                              void* d_out, int out_size) {
    const int*   x     = (const int*)d_in[0];
    const float* core  = (const float*)d_in[1];
    const float* left  = (const float*)d_in[2];
    const float* right = (const float*)d_in[3];
    float* out = (float*)d_out;

    convert_core_kernel<<<32768, NTHR>>>(core);
    init_kernel<<<1, 1024>>>(left, right);
    chain_kernel<<<2 * GRP, NTHR>>>(x, out);
}